// round 15
// baseline (speedup 1.0000x reference)
#include <cuda_runtime.h>
#include <cuda_bf16.h>

#define NG    2048
#define W_IMG 128
#define H_IMG 128
#define HW    16384
#define NB    256         // blocks; 2/SM co-resident (88KB smem) -> barrier safe
#define NT    512         // threads per block -> 32 warps/SM = 8/SMSP

// ---------------- scratch (static device globals) ----------------------------
__device__ float4 g_s0[NG], g_s1[NG];          // depth-sorted params
__device__ float4 g_c[NG];                     // depth-sorted (px,py,R,cb)

__device__ unsigned g_barcnt = 0;
__device__ volatile unsigned g_bargen = 0;

__device__ __forceinline__ void gridbar() {
    __syncthreads();
    if (threadIdx.x == 0) {
        unsigned gen = g_bargen;
        __threadfence();
        unsigned t = atomicAdd(&g_barcnt, 1u);
        if (t == NB - 1) {
            g_barcnt = 0;
            __threadfence();
            g_bargen = gen + 1;
        } else {
            while (g_bargen == gen) { __nanosleep(32); }
        }
    }
    __syncthreads();
}

__device__ __forceinline__ float ex2(float x) {
    float y; asm("ex2.approx.f32 %0, %1;" : "=f"(y) : "f"(x)); return y;
}
__device__ __forceinline__ float lg2(float x) {
    float y; asm("lg2.approx.f32 %0, %1;" : "=f"(y) : "f"(x)); return y;
}
__device__ __forceinline__ float frcp(float x) {
    float y; asm("rcp.approx.f32 %0, %1;" : "=f"(y) : "f"(x)); return y;
}
__device__ __forceinline__ float sig_ap(float x) {
    return frcp(1.0f + ex2(-1.4426950408889634f * x));
}
__device__ __forceinline__ float exp_ap(float x) {
    return ex2(1.4426950408889634f * x);
}
__device__ __forceinline__ unsigned fkey(float f) {
    unsigned u = __float_as_uint(f);
    return (u & 0x80000000u) ? ~u : (u | 0x80000000u);
}

// dynamic smem: keys union concatenated blend survivor list
struct SmemBlend {
    float4 b0[NG];                             // 32 KB
    float4 b1[NG];                             // 32 KB
    float  b2[NG];                             //  8 KB
};
union SmemU {
    unsigned long long keys[NG];               // 16 KB (rank)
    SmemBlend bl;                              // 72 KB (blend)
};
#define SMEM_BYTES (sizeof(SmemU))

__global__ void __launch_bounds__(NT) k_fused(
        const float* __restrict__ pts, const float* __restrict__ scl,
        const float* __restrict__ col, const float* __restrict__ opa,
        const float* __restrict__ rot, const float* __restrict__ view,
        const float* __restrict__ proj, float* __restrict__ out)
{
    extern __shared__ char dynsmem[];
    SmemU& sm = *reinterpret_cast<SmemU*>(dynsmem);
    __shared__ float4 comb[16][64];            // 16 KB static (blend combine)
    __shared__ float4 sp0[8], sp1[8];          // prep results (this block's 8)
    __shared__ float2 sp2[8];
    __shared__ int    partial[16];
    __shared__ int    scnt[16];                // per-warp survivor counts

    int tid  = threadIdx.x;
    int lane = tid & 31;
    int wid  = tid >> 5;

    // ===== phase 1 (overlapped): prep own 8 gaussians  ||  all 2048 keys =====
    if (tid < 8) {
        int i = blockIdx.x * 8 + tid;

        float v[16], pr[16];
#pragma unroll
        for (int k = 0; k < 16; k++) v[k]  = view[k];
#pragma unroll
        for (int k = 0; k < 16; k++) pr[k] = proj[k];

        float p0 = pts[3*i], p1 = pts[3*i+1], p2 = pts[3*i+2];

        float t0 = v[0]*p0 + v[1]*p1 + v[2]*p2  + v[3];
        float t1 = v[4]*p0 + v[5]*p1 + v[6]*p2  + v[7];
        float tz = v[8]*p0 + v[9]*p1 + v[10]*p2 + v[11];

        float q0 = rot[4*i], q1 = rot[4*i+1], q2 = rot[4*i+2], q3 = rot[4*i+3];
        float qn = rsqrtf(q0*q0 + q1*q1 + q2*q2 + q3*q3);
        q0 *= qn; q1 *= qn; q2 *= qn; q3 *= qn;
        float R0 = 1.f - 2.f*(q2*q2 + q3*q3), R1 = 2.f*(q1*q2 - q0*q3), R2 = 2.f*(q1*q3 + q0*q2);
        float R3 = 2.f*(q1*q2 + q0*q3), R4 = 1.f - 2.f*(q1*q1 + q3*q3), R5 = 2.f*(q2*q3 - q0*q1);
        float R6 = 2.f*(q1*q3 - q0*q2), R7 = 2.f*(q2*q3 + q0*q1), R8 = 1.f - 2.f*(q1*q1 + q2*q2);

        float s0 = exp_ap(scl[3*i]), s1 = exp_ap(scl[3*i+1]), s2 = exp_ap(scl[3*i+2]);
        float M0 = R0*s0, M1 = R1*s1, M2 = R2*s2;
        float M3 = R3*s0, M4 = R4*s1, M5 = R5*s2;
        float M6 = R6*s0, M7 = R7*s1, M8 = R8*s2;

        const float fx = 64.f, fy = 64.f;
        float invz = frcp(tz);
        float txz = fminf(fmaxf(t0*invz, -1.3f), 1.3f) * tz;
        float tyz = fminf(fmaxf(t1*invz, -1.3f), 1.3f) * tz;
        float J00 = fx*invz, J02 = -fx*txz*invz*invz;
        float J11 = fy*invz, J12 = -fy*tyz*invz*invz;

        float T00 = J00*v[0] + J02*v[8],  T01 = J00*v[1] + J02*v[9],  T02 = J00*v[2] + J02*v[10];
        float T10 = J11*v[4] + J12*v[8],  T11 = J11*v[5] + J12*v[9],  T12 = J11*v[6] + J12*v[10];

        float X00 = T00*M0 + T01*M3 + T02*M6;
        float X01 = T00*M1 + T01*M4 + T02*M7;
        float X02 = T00*M2 + T01*M5 + T02*M8;
        float X10 = T10*M0 + T11*M3 + T12*M6;
        float X11 = T10*M1 + T11*M4 + T12*M7;
        float X12 = T10*M2 + T11*M5 + T12*M8;

        float a = X00*X00 + X01*X01 + X02*X02 + 0.3f;
        float b = X00*X10 + X01*X11 + X02*X12;
        float c = X10*X10 + X11*X11 + X12*X12 + 0.3f;

        float det   = a*c - b*b;
        bool  valid = (tz > 0.2f) && (det > 0.0f);
        float det_s = (det > 0.0f) ? det : 1.0f;
        float idet  = frcp(det_s);

        const float L2E = 1.4426950408889634f;
        float A2 = -0.5f * c * idet * L2E;
        float C2 = -0.5f * a * idet * L2E;
        float Bq =         b * idet * L2E;

        float mid   = 0.5f * (a + c);
        float lam   = mid + sqrtf(fmaxf(mid*mid - det, 0.1f));
        float sq    = sqrtf(lam);
        float radii = valid ? ceilf(3.0f * sq) : 0.0f;

        float op = valid ? sig_ap(opa[i]) : 0.0f;
        // opacity-aware cull radius: alpha = op*exp(-d^2/(2*lam)) < 1/255 beyond
        float lnt   = 0.6931471805599453f * lg2(255.0f * fmaxf(op, 1e-30f));
        float cullR = (valid && lnt > 0.f) ? 1.001f * sqrtf(2.0f * lnt) * sq : 0.0f;

        float fr0[4], fr1[4], fr3[4];
#pragma unroll
        for (int cc = 0; cc < 4; cc++) {
            fr0[cc] = pr[0]*v[cc]  + pr[1]*v[4+cc]  + pr[2]*v[8+cc]  + pr[3]*v[12+cc];
            fr1[cc] = pr[4]*v[cc]  + pr[5]*v[4+cc]  + pr[6]*v[8+cc]  + pr[7]*v[12+cc];
            fr3[cc] = pr[12]*v[cc] + pr[13]*v[4+cc] + pr[14]*v[8+cc] + pr[15]*v[12+cc];
        }
        float ph0 = fr0[0]*p0 + fr0[1]*p1 + fr0[2]*p2 + fr0[3];
        float ph1 = fr1[0]*p0 + fr1[1]*p1 + fr1[2]*p2 + fr1[3];
        float ph3 = fr3[0]*p0 + fr3[1]*p1 + fr3[2]*p2 + fr3[3];
        float pwn = frcp(ph3 + 1e-7f);
        float px  = ((ph0*pwn + 1.0f) * (float)W_IMG - 1.0f) * 0.5f;
        float py  = ((ph1*pwn + 1.0f) * (float)H_IMG - 1.0f) * 0.5f;

        float cr = sig_ap(col[3*i]);
        float cg = sig_ap(col[3*i+1]);
        float cb = sig_ap(col[3*i+2]);

        sp0[tid] = make_float4(px, py, A2, Bq);
        sp1[tid] = make_float4(C2, op, cr, cg);
        sp2[tid] = make_float2(cb, cullR);

        out[3*HW + i]      = radii;
        out[3*HW + NG + i] = tz;
    } else if (tid >= 32) {
        // block-local keys for ALL gaussians (identical across blocks)
        float v8 = view[8], v9 = view[9], v10 = view[10], v11 = view[11];
        for (int g2 = tid - 32; g2 < NG; g2 += NT - 32) {
            float tzk = fmaf(v8, pts[3*g2],
                        fmaf(v9, pts[3*g2+1],
                        fmaf(v10, pts[3*g2+2], v11)));
            sm.keys[g2] = ((unsigned long long)fkey(tzk) << 32) | (unsigned)g2;
        }
    }
    __syncthreads();   // prep done (smem sp*), keys done (smem keys)

    // ===== phase 2: rank own 8 gaussians (16 warps: 2 per gaussian) ==========
    {
        int g8   = wid & 7;                   // gaussian within block
        int half = wid >> 3;                  // key half [half*1024, +1024)
        int gi   = blockIdx.x * 8 + g8;
        unsigned long long ki = sm.keys[gi];

        int rk = 0;
        int kb = half * 1024;
#pragma unroll 8
        for (int it = 0; it < 32; it++) {
            rk += (sm.keys[kb + it * 32 + lane] < ki) ? 1 : 0;
        }
        rk += __shfl_xor_sync(0xffffffffu, rk, 1);
        rk += __shfl_xor_sync(0xffffffffu, rk, 2);
        rk += __shfl_xor_sync(0xffffffffu, rk, 4);
        rk += __shfl_xor_sync(0xffffffffu, rk, 8);
        rk += __shfl_xor_sync(0xffffffffu, rk, 16);
        if (lane == 0) partial[wid] = rk;
    }
    __syncthreads();

    if (wid < 8 && lane == 0) {
        int rk = partial[wid] + partial[wid + 8];
        float4 p0v = sp0[wid];
        float2 p2v = sp2[wid];
        g_s0[rk] = p0v;
        g_s1[rk] = sp1[wid];
        g_c[rk]  = make_float4(p0v.x, p0v.y, p2v.y, p2v.x);  // (px,py,R,cb)
    }

    gridbar();   // the ONLY grid barrier

    // ==== phase 3: blend, 8x8 tile; cull per warp, BALANCED survivor spans ===
    {
        unsigned lmask = (1u << lane) - 1u;
        int base = wid * 128;                // this warp's cull segment

        int tx = blockIdx.x & 15;            // 16 tiles across
        int ty = blockIdx.x >> 4;            // 16 tiles down
        int col8 = lane & 7;
        int row8 = lane >> 3;
        int pxi  = tx * 8 + col8;
        int pyi0 = ty * 8 + row8;
        float x  = (float)pxi;
        float ya = (float)pyi0;
        float yb = ya + 4.f;
        float x0 = (float)(tx * 8), x1 = x0 + 7.f;
        float y0 = (float)(ty * 8), y1 = y0 + 7.f;

        // ---- warp-local cull of segment [base, base+128) ----
        unsigned mk[4];
#pragma unroll
        for (int kk = 0; kk < 4; kk++) {
            int gidx = base + kk * 32 + lane;
            float4 cc = g_c[gidx];           // (px,py,R,cb)
            float dxc = fmaxf(fmaxf(x0 - cc.x, cc.x - x1), 0.f);
            float dyc = fmaxf(fmaxf(y0 - cc.y, cc.y - y1), 0.f);
            bool p = (cc.z > 0.f) && (dxc*dxc + dyc*dyc <= cc.z*cc.z);
            mk[kk] = __ballot_sync(0xffffffffu, p);
        }
        int wcount = __popc(mk[0]) + __popc(mk[1]) + __popc(mk[2]) + __popc(mk[3]);
        if (lane == 0) scnt[wid] = wcount;
        __syncthreads();

        // cross-warp exclusive prefix (depth order = segment order)
        int cnts[16];
#pragma unroll
        for (int j = 0; j < 16; j++) cnts[j] = scnt[j];
        int total = 0, wbase = 0;
#pragma unroll
        for (int j = 0; j < 16; j++) {
            if (j < wid) wbase += cnts[j];
            total += cnts[j];
        }

        // scatter survivors into the concatenated depth-ordered list
        int pre = wbase;
#pragma unroll
        for (int kk = 0; kk < 4; kk++) {
            unsigned m = mk[kk];
            if (m & (1u << lane)) {
                int gidx = base + kk * 32 + lane;
                int pp   = pre + __popc(m & lmask);
                sm.bl.b0[pp] = g_s0[gidx];
                sm.bl.b1[pp] = g_s1[gidx];
                sm.bl.b2[pp] = g_c[gidx].w;   // cb, L1-hot reload
            }
            pre += __popc(m);
        }
        __syncthreads();

        // ---- balanced spans: warp w blends [w*chunk, min(total,(w+1)*chunk)) ----
        int chunk = (total + 15) >> 4;
        int nlo = wid * chunk;
        int nhi = min(total, nlo + chunk);

        float ra = 0.f, ga = 0.f, ba = 0.f, Ta = 1.f;
        float rb = 0.f, gb = 0.f, bb = 0.f, Tb = 1.f;
#pragma unroll 2
        for (int n = nlo; n < nhi; n++) {
            float4 c0v = sm.bl.b0[n];
            float4 c1v = sm.bl.b1[n];
            float  cbv = sm.bl.b2[n];
            float dx   = x - c0v.x;
            float com  = (c0v.z * dx) * dx;   // A2*dx^2 shared
            float crs  = c0v.w * dx;          // Bq*dx  shared

            float dya = ya - c0v.y;
            float pwa = fmaf(c1v.x * dya, dya, fmaf(crs, dya, com));
            float ea  = ex2(pwa);
            float ala = fminf(c1v.y * ea, 0.99f);
            float wa  = ((pwa <= 0.0f) && (ala >= 0.0039215686f)) ? Ta * ala : 0.0f;
            ra = fmaf(wa, c1v.z, ra);
            ga = fmaf(wa, c1v.w, ga);
            ba = fmaf(wa, cbv,  ba);
            Ta -= wa;

            float dyb = yb - c0v.y;
            float pwb = fmaf(c1v.x * dyb, dyb, fmaf(crs, dyb, com));
            float eb  = ex2(pwb);
            float alb = fminf(c1v.y * eb, 0.99f);
            float wb  = ((pwb <= 0.0f) && (alb >= 0.0039215686f)) ? Tb * alb : 0.0f;
            rb = fmaf(wb, c1v.z, rb);
            gb = fmaf(wb, c1v.w, gb);
            bb = fmaf(wb, cbv,  bb);
            Tb -= wb;
        }

        // ---- combine 16 depth-contiguous chunks ----
        int pix0 = row8 * 8 + col8;           // 0..31
        int pix1 = pix0 + 32;                 // rows 4..7
        comb[wid][pix0] = make_float4(ra, ga, ba, Ta);
        comb[wid][pix1] = make_float4(rb, gb, bb, Tb);
        __syncthreads();

        if (wid == 0) {
#pragma unroll 2
            for (int h = 0; h < 2; h++) {
                int pix = lane + h * 32;
                float Tt = 1.f, rr = 0.f, gg = 0.f, bz = 0.f;
#pragma unroll
                for (int ss = 0; ss < 16; ss++) {
                    float4 f = comb[ss][pix];
                    rr = fmaf(Tt, f.x, rr);
                    gg = fmaf(Tt, f.y, gg);
                    bz = fmaf(Tt, f.z, bz);
                    Tt *= f.w;
                }
                int prow = ty * 8 + (pix >> 3);
                int pcol = tx * 8 + (pix & 7);
                int p = prow * W_IMG + pcol;
                out[p]        = rr;
                out[HW + p]   = gg;
                out[2*HW + p] = bz;
            }
        }
    }
}

// ---------------- launch -----------------------------------------------------
extern "C" void kernel_launch(void* const* d_in, const int* in_sizes, int n_in,
                              void* d_out, int out_size)
{
    const float* pts  = (const float*)d_in[0];
    const float* scl  = (const float*)d_in[1];
    const float* col  = (const float*)d_in[2];
    const float* opa  = (const float*)d_in[3];
    const float* rot  = (const float*)d_in[4];
    const float* view = (const float*)d_in[5];
    const float* proj = (const float*)d_in[6];
    float* out = (float*)d_out;

    static bool attr_set = false;
    if (!attr_set) {
        cudaFuncSetAttribute(k_fused, cudaFuncAttributeMaxDynamicSharedMemorySize,
                             (int)SMEM_BYTES);
        attr_set = true;
    }
    k_fused<<<NB, NT, SMEM_BYTES>>>(pts, scl, col, opa, rot, view, proj, out);
}

// round 16
// speedup vs baseline: 1.0265x; 1.0265x over previous
#include <cuda_runtime.h>
#include <cuda_bf16.h>

#define NG    2048
#define W_IMG 128
#define H_IMG 128
#define HW    16384
#define NB    256         // blocks; 2/SM co-resident (88KB smem) -> barrier safe
#define NT    512         // threads per block -> 32 warps/SM = 8/SMSP

// ---------------- scratch (static device globals) ----------------------------
__device__ float4 g_s0[NG], g_s1[NG];          // depth-sorted params
__device__ float4 g_c[NG];                     // depth-sorted (px,py,R,cb)

__device__ unsigned g_barcnt = 0;
__device__ volatile unsigned g_bargen = 0;

__device__ __forceinline__ void gridbar() {
    __syncthreads();
    if (threadIdx.x == 0) {
        unsigned gen = g_bargen;
        __threadfence();
        unsigned t = atomicAdd(&g_barcnt, 1u);
        if (t == NB - 1) {
            g_barcnt = 0;
            __threadfence();
            g_bargen = gen + 1;
        } else {
            while (g_bargen == gen) { }       // plain spin: no wake granularity
        }
    }
    __syncthreads();
}

__device__ __forceinline__ float ex2(float x) {
    float y; asm("ex2.approx.f32 %0, %1;" : "=f"(y) : "f"(x)); return y;
}
__device__ __forceinline__ float lg2(float x) {
    float y; asm("lg2.approx.f32 %0, %1;" : "=f"(y) : "f"(x)); return y;
}
__device__ __forceinline__ float frcp(float x) {
    float y; asm("rcp.approx.f32 %0, %1;" : "=f"(y) : "f"(x)); return y;
}
__device__ __forceinline__ float sig_ap(float x) {
    return frcp(1.0f + ex2(-1.4426950408889634f * x));
}
__device__ __forceinline__ float exp_ap(float x) {
    return ex2(1.4426950408889634f * x);
}
__device__ __forceinline__ unsigned fkey(float f) {
    unsigned u = __float_as_uint(f);
    return (u & 0x80000000u) ? ~u : (u | 0x80000000u);
}

// dynamic smem: keys union per-warp blend buffers
struct SmemBlend {
    float4 b0[16][128];                        // 32 KB
    float4 b1[16][128];                        // 32 KB
    float  b2[16][128];                        //  8 KB
};
union SmemU {
    unsigned long long keys[NG];               // 16 KB (rank)
    SmemBlend bl;                              // 72 KB (blend)
};
#define SMEM_BYTES (sizeof(SmemU))

__global__ void __launch_bounds__(NT) k_fused(
        const float* __restrict__ pts, const float* __restrict__ scl,
        const float* __restrict__ col, const float* __restrict__ opa,
        const float* __restrict__ rot, const float* __restrict__ view,
        const float* __restrict__ proj, float* __restrict__ out)
{
    extern __shared__ char dynsmem[];
    SmemU& sm = *reinterpret_cast<SmemU*>(dynsmem);
    __shared__ float4 comb[16][64];            // 16 KB static (blend combine)
    __shared__ float4 sp0[8], sp1[8];          // prep results (this block's 8)
    __shared__ float2 sp2[8];
    __shared__ int    partial[16];

    int tid  = threadIdx.x;
    int lane = tid & 31;
    int wid  = tid >> 5;

    // ===== phase 1 (overlapped): prep own 8 gaussians  ||  all 2048 keys =====
    if (tid < 8) {
        int i = blockIdx.x * 8 + tid;

        float v[16], pr[16];
#pragma unroll
        for (int k = 0; k < 16; k++) v[k]  = view[k];
#pragma unroll
        for (int k = 0; k < 16; k++) pr[k] = proj[k];

        float p0 = pts[3*i], p1 = pts[3*i+1], p2 = pts[3*i+2];

        float t0 = v[0]*p0 + v[1]*p1 + v[2]*p2  + v[3];
        float t1 = v[4]*p0 + v[5]*p1 + v[6]*p2  + v[7];
        float tz = v[8]*p0 + v[9]*p1 + v[10]*p2 + v[11];

        float q0 = rot[4*i], q1 = rot[4*i+1], q2 = rot[4*i+2], q3 = rot[4*i+3];
        float qn = rsqrtf(q0*q0 + q1*q1 + q2*q2 + q3*q3);
        q0 *= qn; q1 *= qn; q2 *= qn; q3 *= qn;
        float R0 = 1.f - 2.f*(q2*q2 + q3*q3), R1 = 2.f*(q1*q2 - q0*q3), R2 = 2.f*(q1*q3 + q0*q2);
        float R3 = 2.f*(q1*q2 + q0*q3), R4 = 1.f - 2.f*(q1*q1 + q3*q3), R5 = 2.f*(q2*q3 - q0*q1);
        float R6 = 2.f*(q1*q3 - q0*q2), R7 = 2.f*(q2*q3 + q0*q1), R8 = 1.f - 2.f*(q1*q1 + q2*q2);

        float s0 = exp_ap(scl[3*i]), s1 = exp_ap(scl[3*i+1]), s2 = exp_ap(scl[3*i+2]);
        float M0 = R0*s0, M1 = R1*s1, M2 = R2*s2;
        float M3 = R3*s0, M4 = R4*s1, M5 = R5*s2;
        float M6 = R6*s0, M7 = R7*s1, M8 = R8*s2;

        const float fx = 64.f, fy = 64.f;
        float invz = frcp(tz);
        float txz = fminf(fmaxf(t0*invz, -1.3f), 1.3f) * tz;
        float tyz = fminf(fmaxf(t1*invz, -1.3f), 1.3f) * tz;
        float J00 = fx*invz, J02 = -fx*txz*invz*invz;
        float J11 = fy*invz, J12 = -fy*tyz*invz*invz;

        float T00 = J00*v[0] + J02*v[8],  T01 = J00*v[1] + J02*v[9],  T02 = J00*v[2] + J02*v[10];
        float T10 = J11*v[4] + J12*v[8],  T11 = J11*v[5] + J12*v[9],  T12 = J11*v[6] + J12*v[10];

        float X00 = T00*M0 + T01*M3 + T02*M6;
        float X01 = T00*M1 + T01*M4 + T02*M7;
        float X02 = T00*M2 + T01*M5 + T02*M8;
        float X10 = T10*M0 + T11*M3 + T12*M6;
        float X11 = T10*M1 + T11*M4 + T12*M7;
        float X12 = T10*M2 + T11*M5 + T12*M8;

        float a = X00*X00 + X01*X01 + X02*X02 + 0.3f;
        float b = X00*X10 + X01*X11 + X02*X12;
        float c = X10*X10 + X11*X11 + X12*X12 + 0.3f;

        float det   = a*c - b*b;
        bool  valid = (tz > 0.2f) && (det > 0.0f);
        float det_s = (det > 0.0f) ? det : 1.0f;
        float idet  = frcp(det_s);

        const float L2E = 1.4426950408889634f;
        float A2 = -0.5f * c * idet * L2E;
        float C2 = -0.5f * a * idet * L2E;
        float Bq =         b * idet * L2E;

        float mid   = 0.5f * (a + c);
        float lam   = mid + sqrtf(fmaxf(mid*mid - det, 0.1f));
        float sq    = sqrtf(lam);
        float radii = valid ? ceilf(3.0f * sq) : 0.0f;

        float op = valid ? sig_ap(opa[i]) : 0.0f;
        // opacity-aware cull radius: alpha = op*exp(-d^2/(2*lam)) < 1/255 beyond
        float lnt   = 0.6931471805599453f * lg2(255.0f * fmaxf(op, 1e-30f));
        float cullR = (valid && lnt > 0.f) ? 1.001f * sqrtf(2.0f * lnt) * sq : 0.0f;

        float fr0[4], fr1[4], fr3[4];
#pragma unroll
        for (int cc = 0; cc < 4; cc++) {
            fr0[cc] = pr[0]*v[cc]  + pr[1]*v[4+cc]  + pr[2]*v[8+cc]  + pr[3]*v[12+cc];
            fr1[cc] = pr[4]*v[cc]  + pr[5]*v[4+cc]  + pr[6]*v[8+cc]  + pr[7]*v[12+cc];
            fr3[cc] = pr[12]*v[cc] + pr[13]*v[4+cc] + pr[14]*v[8+cc] + pr[15]*v[12+cc];
        }
        float ph0 = fr0[0]*p0 + fr0[1]*p1 + fr0[2]*p2 + fr0[3];
        float ph1 = fr1[0]*p0 + fr1[1]*p1 + fr1[2]*p2 + fr1[3];
        float ph3 = fr3[0]*p0 + fr3[1]*p1 + fr3[2]*p2 + fr3[3];
        float pwn = frcp(ph3 + 1e-7f);
        float px  = ((ph0*pwn + 1.0f) * (float)W_IMG - 1.0f) * 0.5f;
        float py  = ((ph1*pwn + 1.0f) * (float)H_IMG - 1.0f) * 0.5f;

        float cr = sig_ap(col[3*i]);
        float cg = sig_ap(col[3*i+1]);
        float cb = sig_ap(col[3*i+2]);

        // invalid/culled gaussians: park center far away so the distance test
        // fails without needing an R>0 compare in the hot cull loop
        if (cullR <= 0.f) { px = 1e9f; py = 1e9f; cullR = 0.f; }

        sp0[tid] = make_float4(px, py, A2, Bq);
        sp1[tid] = make_float4(C2, op, cr, cg);
        sp2[tid] = make_float2(cb, cullR);

        out[3*HW + i]      = radii;
        out[3*HW + NG + i] = tz;
    } else if (tid >= 32) {
        // block-local keys for ALL gaussians (identical across blocks)
        float v8 = view[8], v9 = view[9], v10 = view[10], v11 = view[11];
        for (int g2 = tid - 32; g2 < NG; g2 += NT - 32) {
            float tzk = fmaf(v8, pts[3*g2],
                        fmaf(v9, pts[3*g2+1],
                        fmaf(v10, pts[3*g2+2], v11)));
            sm.keys[g2] = ((unsigned long long)fkey(tzk) << 32) | (unsigned)g2;
        }
    }
    __syncthreads();   // prep done (smem sp*), keys done (smem keys)

    // ===== phase 2: rank own 8 gaussians (16 warps: 2 per gaussian) ==========
    {
        int g8   = wid & 7;                   // gaussian within block
        int half = wid >> 3;                  // key half [half*1024, +1024)
        int gi   = blockIdx.x * 8 + g8;
        unsigned long long ki = sm.keys[gi];

        int rk = 0;
        int kb = half * 1024;
#pragma unroll 8
        for (int it = 0; it < 32; it++) {
            rk += (sm.keys[kb + it * 32 + lane] < ki) ? 1 : 0;
        }
        rk += __shfl_xor_sync(0xffffffffu, rk, 1);
        rk += __shfl_xor_sync(0xffffffffu, rk, 2);
        rk += __shfl_xor_sync(0xffffffffu, rk, 4);
        rk += __shfl_xor_sync(0xffffffffu, rk, 8);
        rk += __shfl_xor_sync(0xffffffffu, rk, 16);
        if (lane == 0) partial[wid] = rk;
    }
    __syncthreads();

    if (wid < 8 && lane == 0) {
        int rk = partial[wid] + partial[wid + 8];
        float4 p0v = sp0[wid];
        float2 p2v = sp2[wid];
        g_s0[rk] = p0v;
        g_s1[rk] = sp1[wid];
        g_c[rk]  = make_float4(p0v.x, p0v.y, p2v.y, p2v.x);  // (px,py,R,cb)
    }

    gridbar();   // the ONLY grid barrier

    // ==== phase 3: blend, 8x8 tile, warp = 128-gaussian depth segment ========
    {
        unsigned lmask = (1u << lane) - 1u;
        int base = wid * 128;

        int tx = blockIdx.x & 15;            // 16 tiles across
        int ty = blockIdx.x >> 4;            // 16 tiles down
        // 2 pixels per lane, same column: rows (lane>>3) and (lane>>3)+4
        int col8 = lane & 7;
        int row8 = lane >> 3;
        int pxi  = tx * 8 + col8;
        int pyi0 = ty * 8 + row8;
        float x  = (float)pxi;
        float ya = (float)pyi0;
        float yb = ya + 4.f;
        float x0 = (float)(tx * 8), x1 = x0 + 7.f;
        float y0 = (float)(ty * 8), y1 = y0 + 7.f;

        // ---- warp-local cull: 4 gaussians per lane, one LDG.128 each ----
        unsigned mk[4];
#pragma unroll
        for (int kk = 0; kk < 4; kk++) {
            int gidx = base + kk * 32 + lane;
            float4 cc = g_c[gidx];           // (px,py,R,cb); invalid => px=1e9
            float dxc = fmaxf(fmaxf(x0 - cc.x, cc.x - x1), 0.f);
            float dyc = fmaxf(fmaxf(y0 - cc.y, cc.y - y1), 0.f);
            bool p = (dxc*dxc + dyc*dyc <= cc.z*cc.z);
            mk[kk] = __ballot_sync(0xffffffffu, p);
        }

        int pre = 0;
#pragma unroll
        for (int kk = 0; kk < 4; kk++) {
            unsigned m = mk[kk];
            if (m & (1u << lane)) {
                int gidx = base + kk * 32 + lane;
                int pp   = pre + __popc(m & lmask);
                sm.bl.b0[wid][pp] = g_s0[gidx];
                sm.bl.b1[wid][pp] = g_s1[gidx];
                sm.bl.b2[wid][pp] = g_c[gidx].w;   // cb, L1-hot reload
            }
            pre += __popc(m);
        }
        int cnt = pre;
        __syncwarp();

        // ---- blend survivors for 2 pixels (independent T-chains) ----
        float ra = 0.f, ga = 0.f, ba = 0.f, Ta = 1.f;
        float rb = 0.f, gb = 0.f, bb = 0.f, Tb = 1.f;
#pragma unroll 4
        for (int n = 0; n < cnt; n++) {
            float4 c0v = sm.bl.b0[wid][n];
            float4 c1v = sm.bl.b1[wid][n];
            float  cbv = sm.bl.b2[wid][n];
            float dx   = x - c0v.x;
            float com  = (c0v.z * dx) * dx;   // A2*dx^2 shared
            float crs  = c0v.w * dx;          // Bq*dx  shared

            float dya = ya - c0v.y;
            float pwa = fmaf(c1v.x * dya, dya, fmaf(crs, dya, com));
            float ea  = ex2(pwa);
            float ala = fminf(c1v.y * ea, 0.99f);
            float wa  = ((pwa <= 0.0f) && (ala >= 0.0039215686f)) ? Ta * ala : 0.0f;
            ra = fmaf(wa, c1v.z, ra);
            ga = fmaf(wa, c1v.w, ga);
            ba = fmaf(wa, cbv,  ba);
            Ta -= wa;

            float dyb = yb - c0v.y;
            float pwb = fmaf(c1v.x * dyb, dyb, fmaf(crs, dyb, com));
            float eb  = ex2(pwb);
            float alb = fminf(c1v.y * eb, 0.99f);
            float wb  = ((pwb <= 0.0f) && (alb >= 0.0039215686f)) ? Tb * alb : 0.0f;
            rb = fmaf(wb, c1v.z, rb);
            gb = fmaf(wb, c1v.w, gb);
            bb = fmaf(wb, cbv,  bb);
            Tb -= wb;
        }

        // ---- combine 16 depth segments (warps 0 and 1 split the halves) ----
        int pix0 = row8 * 8 + col8;           // 0..31
        int pix1 = pix0 + 32;                 // rows 4..7
        comb[wid][pix0] = make_float4(ra, ga, ba, Ta);
        comb[wid][pix1] = make_float4(rb, gb, bb, Tb);
        __syncthreads();

        if (wid < 2) {
            int pix = lane + wid * 32;
            float Tt = 1.f, rr = 0.f, gg = 0.f, bz = 0.f;
#pragma unroll
            for (int ss = 0; ss < 16; ss++) {
                float4 f = comb[ss][pix];
                rr = fmaf(Tt, f.x, rr);
                gg = fmaf(Tt, f.y, gg);
                bz = fmaf(Tt, f.z, bz);
                Tt *= f.w;
            }
            int prow = ty * 8 + (pix >> 3);
            int pcol = tx * 8 + (pix & 7);
            int p = prow * W_IMG + pcol;
            out[p]        = rr;
            out[HW + p]   = gg;
            out[2*HW + p] = bz;
        }
    }
}

// ---------------- launch -----------------------------------------------------
extern "C" void kernel_launch(void* const* d_in, const int* in_sizes, int n_in,
                              void* d_out, int out_size)
{
    const float* pts  = (const float*)d_in[0];
    const float* scl  = (const float*)d_in[1];
    const float* col  = (const float*)d_in[2];
    const float* opa  = (const float*)d_in[3];
    const float* rot  = (const float*)d_in[4];
    const float* view = (const float*)d_in[5];
    const float* proj = (const float*)d_in[6];
    float* out = (float*)d_out;

    static bool attr_set = false;
    if (!attr_set) {
        cudaFuncSetAttribute(k_fused, cudaFuncAttributeMaxDynamicSharedMemorySize,
                             (int)SMEM_BYTES);
        attr_set = true;
    }
    k_fused<<<NB, NT, SMEM_BYTES>>>(pts, scl, col, opa, rot, view, proj, out);
}